// round 1
// baseline (speedup 1.0000x reference)
#include <cuda_runtime.h>
#include <cuda_bf16.h>
#include <math.h>

// Problem dims (fixed by the dataset)
#define T_STEPS 512
#define B_SZ    64
#define D_SZ    256
#define H_SZ    256
#define ALPHA   0.9f

// Scratch for the precomputed input GEMM: xw[t][b][h] = inputs[t,b,:]@W_in + b
__device__ float g_xw[(size_t)T_STEPS * B_SZ * H_SZ];

// ---------------------------------------------------------------------------
// Tiled fp32 GEMM: C[M,256] = A[M,256] @ Bm[256,256] (+ bias), tiles 128x128,
// BK=8, 256 threads, 8x8 per thread (split 4+4 to keep LDS.128 conflict-free).
// ---------------------------------------------------------------------------
__global__ __launch_bounds__(256) void sgemm_k(
    const float* __restrict__ A, const float* __restrict__ Bm,
    const float* __restrict__ bias, float* __restrict__ C)
{
    const int K = 256, N = 256;
    __shared__ float As[2][8][128];
    __shared__ float Bs[2][8][128];

    const int tid = threadIdx.x;
    const int bm = blockIdx.x * 128;
    const int bn = blockIdx.y * 128;
    const int tx = tid & 15;       // 16 cols groups
    const int ty = tid >> 4;       // 16 row groups

    // global load mapping
    const int a_m = tid >> 1;            // 0..127
    const int a_k = (tid & 1) * 4;       // 0 or 4
    const int b_k = tid >> 5;            // 0..7
    const int b_n = (tid & 31) * 4;      // 0..124

    const float* Ap = A + (size_t)(bm + a_m) * K + a_k;
    const float* Bp = Bm + (size_t)b_k * N + bn + b_n;

    float4 af = *(const float4*)Ap;
    float4 bf = *(const float4*)Bp;

    float acc[8][8];
#pragma unroll
    for (int i = 0; i < 8; i++)
#pragma unroll
        for (int j = 0; j < 8; j++) acc[i][j] = 0.f;

    int buf = 0;
    for (int kt = 0; kt < K; kt += 8) {
        As[buf][a_k + 0][a_m] = af.x;
        As[buf][a_k + 1][a_m] = af.y;
        As[buf][a_k + 2][a_m] = af.z;
        As[buf][a_k + 3][a_m] = af.w;
        *(float4*)&Bs[buf][b_k][b_n] = bf;
        __syncthreads();
        if (kt + 8 < K) {
            af = *(const float4*)(Ap + kt + 8);
            bf = *(const float4*)(Bp + (size_t)(kt + 8) * N);
        }
#pragma unroll
        for (int k = 0; k < 8; k++) {
            float a0[4], a1[4], b0[4], b1[4];
            *(float4*)a0 = *(const float4*)&As[buf][k][ty * 4];
            *(float4*)a1 = *(const float4*)&As[buf][k][64 + ty * 4];
            *(float4*)b0 = *(const float4*)&Bs[buf][k][tx * 4];
            *(float4*)b1 = *(const float4*)&Bs[buf][k][64 + tx * 4];
#pragma unroll
            for (int i = 0; i < 4; i++)
#pragma unroll
                for (int j = 0; j < 4; j++) {
                    acc[i][j]         += a0[i] * b0[j];
                    acc[i][j + 4]     += a0[i] * b1[j];
                    acc[i + 4][j]     += a1[i] * b0[j];
                    acc[i + 4][j + 4] += a1[i] * b1[j];
                }
        }
        buf ^= 1;
    }

    float bv0[4], bv1[4];
#pragma unroll
    for (int j = 0; j < 4; j++) {
        bv0[j] = bias ? bias[bn + tx * 4 + j]      : 0.f;
        bv1[j] = bias ? bias[bn + 64 + tx * 4 + j] : 0.f;
    }

#pragma unroll
    for (int i = 0; i < 8; i++) {
        int r = bm + ((i < 4) ? (ty * 4 + i) : (64 + ty * 4 + (i - 4)));
        float4 o0, o1;
        o0.x = acc[i][0] + bv0[0]; o0.y = acc[i][1] + bv0[1];
        o0.z = acc[i][2] + bv0[2]; o0.w = acc[i][3] + bv0[3];
        o1.x = acc[i][4] + bv1[0]; o1.y = acc[i][5] + bv1[1];
        o1.z = acc[i][6] + bv1[2]; o1.w = acc[i][7] + bv1[3];
        *(float4*)&C[(size_t)r * N + bn + tx * 4]      = o0;
        *(float4*)&C[(size_t)r * N + bn + 64 + tx * 4] = o1;
    }
}

// ---------------------------------------------------------------------------
// Sequential scan: 64 CTAs (one per batch row), 256 threads (one per h).
// W_rec rows [0,SMK) live in shared memory; rows [SMK,256) live in registers
// (thread t holds column t). One __syncthreads per step (double-buffered s).
// ---------------------------------------------------------------------------
#define SMK 128   // W_rec rows kept in smem; 256-SMK rows kept in registers

__global__ __launch_bounds__(256, 1) void scan_kernel(
    const float* __restrict__ W_rec, const float* __restrict__ spike0,
    const float* __restrict__ v0,    const float* __restrict__ xw,
    float* __restrict__ spikes, float* __restrict__ probs,
    float* __restrict__ vT, float* __restrict__ sT)
{
    extern __shared__ float dynsm[];
    float* w_sm = dynsm;                 // [SMK * 256]
    float* sbuf = dynsm + SMK * 256;     // [2][256]

    const int t   = threadIdx.x;   // output column h
    const int row = blockIdx.x;    // batch row b

    // Stage W_rec rows [0, SMK) into smem (coalesced)
    for (int i = t; i < SMK * 256; i += 256) w_sm[i] = W_rec[i];

    // Register-resident W_rec rows [SMK, 256), column t
    float wreg[256 - SMK];
#pragma unroll
    for (int j = 0; j < 256 - SMK; j++) wreg[j] = W_rec[(size_t)(SMK + j) * 256 + t];

    const float s0 = spike0[row * 256 + t];
    sbuf[t] = s0;
    spikes[(size_t)row * 256 + t] = s0;          // spikes[0] = spike0
    float v = v0[row * 256 + t];
    __syncthreads();

    const float* xwp = xw + (size_t)row * 256 + t;
    int cur = 0;
    float prob = s0;

    for (int step = 0; step < T_STEPS; step++) {
        const float xval = __ldg(xwp + (size_t)step * (B_SZ * H_SZ));
        const float* s = sbuf + cur * 256;

        float acc = 0.f;
        // smem half of W_rec
#pragma unroll 4
        for (int k = 0; k < SMK; k += 4) {
            float4 sv = *(const float4*)(s + k);
            acc += sv.x * w_sm[(k + 0) * 256 + t];
            acc += sv.y * w_sm[(k + 1) * 256 + t];
            acc += sv.z * w_sm[(k + 2) * 256 + t];
            acc += sv.w * w_sm[(k + 3) * 256 + t];
        }
        // register half of W_rec
#pragma unroll
        for (int j = 0; j < 256 - SMK; j += 4) {
            float4 sv = *(const float4*)(s + SMK + j);
            acc += sv.x * wreg[j + 0];
            acc += sv.y * wreg[j + 1];
            acc += sv.z * wreg[j + 2];
            acc += sv.w * wreg[j + 3];
        }

        v = ALPHA * v + xval + acc;
        prob = 1.0f / (1.0f + expf(-v));

        const size_t off = ((size_t)step * B_SZ + row) * 256 + t;
        probs[off] = prob;                       // probs[step]
        spikes[off + (size_t)B_SZ * 256] = prob; // spikes[step+1]

        sbuf[(cur ^ 1) * 256 + t] = prob;
        __syncthreads();
        cur ^= 1;
    }

    vT[row * 256 + t] = v;
    sT[row * 256 + t] = prob;
}

// ---------------------------------------------------------------------------
// Launch: GEMM(xw) -> scan -> GEMM(preds). All stream-ordered, capture-safe.
// ---------------------------------------------------------------------------
extern "C" void kernel_launch(void* const* d_in, const int* in_sizes, int n_in,
                              void* d_out, int out_size)
{
    const float* inputs = (const float*)d_in[0];  // [512,64,256]
    const float* spike0 = (const float*)d_in[1];  // [64,256]
    const float* v0     = (const float*)d_in[2];  // [64,256]
    const float* W_in   = (const float*)d_in[3];  // [256,256]
    const float* W_rec  = (const float*)d_in[4];  // [256,256]
    const float* W_out  = (const float*)d_in[5];  // [256,256]
    const float* bvec   = (const float*)d_in[6];  // [256]

    float* out = (float*)d_out;
    // output packing: spikes[513,64,256], preds[512,64,256], probs[512,64,256], v_T, s_T
    float* spikes = out;
    float* preds  = out + (size_t)513 * B_SZ * H_SZ;                       //  8404992
    float* probs  = preds + (size_t)T_STEPS * B_SZ * H_SZ;                 // 16793600
    float* vT     = probs + (size_t)T_STEPS * B_SZ * H_SZ;                 // 25182208
    float* sT     = vT + (size_t)B_SZ * H_SZ;                              // 25198592

    float* xw = nullptr;
    cudaGetSymbolAddress((void**)&xw, g_xw);

    const size_t scan_smem = (size_t)(SMK * 256 + 2 * 256) * sizeof(float);
    cudaFuncSetAttribute(scan_kernel, cudaFuncAttributeMaxDynamicSharedMemorySize,
                         (int)scan_smem);

    dim3 gemm_grid((T_STEPS * B_SZ) / 128, H_SZ / 128);  // (256, 2)

    // 1) xw = inputs @ W_in + b
    sgemm_k<<<gemm_grid, 256>>>(inputs, W_in, bvec, xw);

    // 2) sequential scan (writes spikes, probs, vT, sT)
    scan_kernel<<<B_SZ, 256, scan_smem>>>(W_rec, spike0, v0, xw,
                                          spikes, probs, vT, sT);

    // 3) preds = spikes[1:] @ W_out
    sgemm_k<<<gemm_grid, 256>>>(spikes + (size_t)B_SZ * H_SZ, W_out, nullptr, preds);
}

// round 3
// speedup vs baseline: 1.2667x; 1.2667x over previous
#include <cuda_runtime.h>
#include <cuda_bf16.h>
#include <cstdint>
#include <math.h>

// Problem dims (fixed by the dataset)
#define T_STEPS 512
#define B_SZ    64
#define D_SZ    256
#define H_SZ    256
#define ALPHA   0.9f

// Scratch for the precomputed input GEMM: xw[t][b][h] = inputs[t,b,:]@W_in + b
__device__ float g_xw[(size_t)T_STEPS * B_SZ * H_SZ];

// ---------------------------------------------------------------------------
// Tiled fp32 GEMM: C[M,256] = A[M,256] @ Bm[256,256] (+ bias), tiles 128x128,
// BK=8, 256 threads, 8x8 per thread.
// ---------------------------------------------------------------------------
__global__ __launch_bounds__(256) void sgemm_k(
    const float* __restrict__ A, const float* __restrict__ Bm,
    const float* __restrict__ bias, float* __restrict__ C)
{
    const int K = 256, N = 256;
    __shared__ float As[2][8][128];
    __shared__ float Bs[2][8][128];

    const int tid = threadIdx.x;
    const int bm = blockIdx.x * 128;
    const int bn = blockIdx.y * 128;
    const int tx = tid & 15;
    const int ty = tid >> 4;

    const int a_m = tid >> 1;
    const int a_k = (tid & 1) * 4;
    const int b_k = tid >> 5;
    const int b_n = (tid & 31) * 4;

    const float* Ap = A + (size_t)(bm + a_m) * K + a_k;
    const float* Bp = Bm + (size_t)b_k * N + bn + b_n;

    float4 af = *(const float4*)Ap;
    float4 bf = *(const float4*)Bp;

    float acc[8][8];
#pragma unroll
    for (int i = 0; i < 8; i++)
#pragma unroll
        for (int j = 0; j < 8; j++) acc[i][j] = 0.f;

    int buf = 0;
    for (int kt = 0; kt < K; kt += 8) {
        As[buf][a_k + 0][a_m] = af.x;
        As[buf][a_k + 1][a_m] = af.y;
        As[buf][a_k + 2][a_m] = af.z;
        As[buf][a_k + 3][a_m] = af.w;
        *(float4*)&Bs[buf][b_k][b_n] = bf;
        __syncthreads();
        if (kt + 8 < K) {
            af = *(const float4*)(Ap + kt + 8);
            bf = *(const float4*)(Bp + (size_t)(kt + 8) * N);
        }
#pragma unroll
        for (int k = 0; k < 8; k++) {
            float a0[4], a1[4], b0[4], b1[4];
            *(float4*)a0 = *(const float4*)&As[buf][k][ty * 4];
            *(float4*)a1 = *(const float4*)&As[buf][k][64 + ty * 4];
            *(float4*)b0 = *(const float4*)&Bs[buf][k][tx * 4];
            *(float4*)b1 = *(const float4*)&Bs[buf][k][64 + tx * 4];
#pragma unroll
            for (int i = 0; i < 4; i++)
#pragma unroll
                for (int j = 0; j < 4; j++) {
                    acc[i][j]         += a0[i] * b0[j];
                    acc[i][j + 4]     += a0[i] * b1[j];
                    acc[i + 4][j]     += a1[i] * b0[j];
                    acc[i + 4][j + 4] += a1[i] * b1[j];
                }
        }
        buf ^= 1;
    }

    float bv0[4], bv1[4];
#pragma unroll
    for (int j = 0; j < 4; j++) {
        bv0[j] = bias ? bias[bn + tx * 4 + j]      : 0.f;
        bv1[j] = bias ? bias[bn + 64 + tx * 4 + j] : 0.f;
    }

#pragma unroll
    for (int i = 0; i < 8; i++) {
        int r = bm + ((i < 4) ? (ty * 4 + i) : (64 + ty * 4 + (i - 4)));
        float4 o0, o1;
        o0.x = acc[i][0] + bv0[0]; o0.y = acc[i][1] + bv0[1];
        o0.z = acc[i][2] + bv0[2]; o0.w = acc[i][3] + bv0[3];
        o1.x = acc[i][4] + bv1[0]; o1.y = acc[i][5] + bv1[1];
        o1.z = acc[i][6] + bv1[2]; o1.w = acc[i][7] + bv1[3];
        *(float4*)&C[(size_t)r * N + bn + tx * 4]      = o0;
        *(float4*)&C[(size_t)r * N + bn + 64 + tx * 4] = o1;
    }
}

// ---------------------------------------------------------------------------
// Sequential scan, 2-CTA cluster per batch row.
// Cluster pair (2b, 2b+1): rank r computes output columns [r*128, r*128+128).
// 256 threads per CTA: thread i -> column cl = i&127, k-half = i>>7.
// Each thread holds its 128 W_rec values in REGISTERS (no W smem traffic).
// Spike vector double-buffered in smem; peer half delivered via DSMEM store;
// one barrier.cluster per step (release/acquire at cluster scope).
// ---------------------------------------------------------------------------
__global__ __launch_bounds__(256, 1) __cluster_dims__(2, 1, 1)
void scan_kernel(
    const float* __restrict__ W_rec, const float* __restrict__ spike0,
    const float* __restrict__ v0,    const float* __restrict__ xw,
    float* __restrict__ spikes, float* __restrict__ probs,
    float* __restrict__ vT, float* __restrict__ sT)
{
    __shared__ float sbuf[2][256];   // double-buffered full spike vector
    __shared__ float part[128];      // k-half partial sums

    const int i    = threadIdx.x;
    const int cl   = i & 127;        // local column
    const int half = i >> 7;         // k-half: 0 -> k[0,128), 1 -> k[128,256)
    const int row  = blockIdx.x >> 1;   // batch row
    const int rank = blockIdx.x & 1;    // cluster rank
    const int col  = rank * 128 + cl;   // global output column

    // Register-resident W_rec slice: rows [half*128, half*128+128), column col
    float wreg[128];
#pragma unroll
    for (int j = 0; j < 128; j++)
        wreg[j] = W_rec[(size_t)(half * 128 + j) * 256 + col];

    // Init spike buffer (full vector, both CTAs load all 256)
    sbuf[0][i] = spike0[row * 256 + i];
    // spikes[0] = spike0 (both CTAs write identical values; benign)
    spikes[(size_t)row * 256 + i] = spike0[row * 256 + i];

    float v = 0.f, prob = 0.f;
    if (half == 0) {
        v = v0[row * 256 + col];
        prob = spike0[row * 256 + col];
    }

    // Remote smem base of peer CTA's sbuf
    uint32_t sbuf_u32;
    {
        uint64_t tmp;
        asm("cvta.to.shared.u64 %0, %1;" : "=l"(tmp) : "l"((void*)&sbuf[0][0]));
        sbuf_u32 = (uint32_t)tmp;
    }
    uint32_t peer_rank = rank ^ 1;
    uint32_t remote_sbuf;
    asm("mapa.shared::cluster.u32 %0, %1, %2;"
        : "=r"(remote_sbuf) : "r"(sbuf_u32), "r"(peer_rank));

    const float* xwp = xw + (size_t)row * 256 + col;   // only half==0 uses it
    float xnext = (half == 0) ? __ldg(xwp) : 0.f;

    // Make sbuf[0] init visible cluster-wide before first step
    asm volatile("barrier.cluster.arrive.aligned;" ::: "memory");
    asm volatile("barrier.cluster.wait.aligned;"   ::: "memory");

    int cur = 0;
    for (int step = 0; step < T_STEPS; step++) {
        const float xval = xnext;
        if (half == 0 && step + 1 < T_STEPS)
            xnext = __ldg(xwp + (size_t)(step + 1) * (B_SZ * H_SZ));

        // Dot product over this thread's k-half (W in regs, s broadcast LDS)
        const float* s = &sbuf[cur][half * 128];
        float acc = 0.f;
#pragma unroll
        for (int j = 0; j < 128; j += 4) {
            float4 sv = *(const float4*)(s + j);
            acc += sv.x * wreg[j + 0];
            acc += sv.y * wreg[j + 1];
            acc += sv.z * wreg[j + 2];
            acc += sv.w * wreg[j + 3];
        }

        if (half == 1) part[cl] = acc;
        __syncthreads();

        const int nxt = cur ^ 1;
        if (half == 0) {
            float tot = acc + part[cl];
            v = ALPHA * v + xval + tot;
            prob = 1.0f / (1.0f + __expf(-v));

            const size_t off = ((size_t)step * B_SZ + row) * 256 + col;
            probs[off] = prob;                        // probs[step]
            spikes[off + (size_t)B_SZ * 256] = prob;  // spikes[step+1]

            // local spike buffer
            sbuf[nxt][col] = prob;
            // peer CTA's spike buffer (DSMEM store)
            uint32_t raddr = remote_sbuf + (uint32_t)((nxt * 256 + col) * 4);
            asm volatile("st.shared::cluster.f32 [%0], %1;"
                         :: "r"(raddr), "f"(prob) : "memory");
        }

        // Cluster barrier: release all smem/DSMEM writes, acquire peer's
        asm volatile("barrier.cluster.arrive.aligned;" ::: "memory");
        asm volatile("barrier.cluster.wait.aligned;"   ::: "memory");
        cur = nxt;
    }

    if (half == 0) {
        vT[row * 256 + col] = v;
        sT[row * 256 + col] = prob;
    }
}

// ---------------------------------------------------------------------------
// Launch: GEMM(xw) -> scan -> GEMM(preds). All stream-ordered, capture-safe.
// ---------------------------------------------------------------------------
extern "C" void kernel_launch(void* const* d_in, const int* in_sizes, int n_in,
                              void* d_out, int out_size)
{
    const float* inputs = (const float*)d_in[0];  // [512,64,256]
    const float* spike0 = (const float*)d_in[1];  // [64,256]
    const float* v0     = (const float*)d_in[2];  // [64,256]
    const float* W_in   = (const float*)d_in[3];  // [256,256]
    const float* W_rec  = (const float*)d_in[4];  // [256,256]
    const float* W_out  = (const float*)d_in[5];  // [256,256]
    const float* bvec   = (const float*)d_in[6];  // [256]

    float* out = (float*)d_out;
    float* spikes = out;
    float* preds  = out + (size_t)513 * B_SZ * H_SZ;
    float* probs  = preds + (size_t)T_STEPS * B_SZ * H_SZ;
    float* vT     = probs + (size_t)T_STEPS * B_SZ * H_SZ;
    float* sT     = vT + (size_t)B_SZ * H_SZ;

    float* xw = nullptr;
    cudaGetSymbolAddress((void**)&xw, g_xw);

    dim3 gemm_grid((T_STEPS * B_SZ) / 128, H_SZ / 128);  // (256, 2)

    // 1) xw = inputs @ W_in + b
    sgemm_k<<<gemm_grid, 256>>>(inputs, W_in, bvec, xw);

    // 2) sequential scan (128 CTAs = 64 clusters of 2)
    scan_kernel<<<2 * B_SZ, 256>>>(W_rec, spike0, v0, xw,
                                   spikes, probs, vT, sT);

    // 3) preds = spikes[1:] @ W_out
    sgemm_k<<<gemm_grid, 256>>>(spikes + (size_t)B_SZ * H_SZ, W_out, nullptr, preds);
}

// round 4
// speedup vs baseline: 1.3085x; 1.0330x over previous
#include <cuda_runtime.h>
#include <cuda_bf16.h>
#include <cstdint>
#include <math.h>

// Problem dims (fixed by the dataset)
#define T_STEPS 512
#define B_SZ    64
#define D_SZ    256
#define H_SZ    256
#define ALPHA   0.9f

// Scratch for the precomputed input GEMM: xw[t][b][h] = inputs[t,b,:]@W_in + b
__device__ float g_xw[(size_t)T_STEPS * B_SZ * H_SZ];

// ---------------------------------------------------------------------------
// Tiled fp32 GEMM: C[M,256] = A[M,256] @ Bm[256,256] (+ bias), tiles 128x128,
// BK=8, 256 threads, 8x8 per thread.
// ---------------------------------------------------------------------------
__global__ __launch_bounds__(256) void sgemm_k(
    const float* __restrict__ A, const float* __restrict__ Bm,
    const float* __restrict__ bias, float* __restrict__ C)
{
    const int K = 256, N = 256;
    __shared__ float As[2][8][128];
    __shared__ float Bs[2][8][128];

    const int tid = threadIdx.x;
    const int bm = blockIdx.x * 128;
    const int bn = blockIdx.y * 128;
    const int tx = tid & 15;
    const int ty = tid >> 4;

    const int a_m = tid >> 1;
    const int a_k = (tid & 1) * 4;
    const int b_k = tid >> 5;
    const int b_n = (tid & 31) * 4;

    const float* Ap = A + (size_t)(bm + a_m) * K + a_k;
    const float* Bp = Bm + (size_t)b_k * N + bn + b_n;

    float4 af = *(const float4*)Ap;
    float4 bf = *(const float4*)Bp;

    float acc[8][8];
#pragma unroll
    for (int i = 0; i < 8; i++)
#pragma unroll
        for (int j = 0; j < 8; j++) acc[i][j] = 0.f;

    int buf = 0;
    for (int kt = 0; kt < K; kt += 8) {
        As[buf][a_k + 0][a_m] = af.x;
        As[buf][a_k + 1][a_m] = af.y;
        As[buf][a_k + 2][a_m] = af.z;
        As[buf][a_k + 3][a_m] = af.w;
        *(float4*)&Bs[buf][b_k][b_n] = bf;
        __syncthreads();
        if (kt + 8 < K) {
            af = *(const float4*)(Ap + kt + 8);
            bf = *(const float4*)(Bp + (size_t)(kt + 8) * N);
        }
#pragma unroll
        for (int k = 0; k < 8; k++) {
            float a0[4], a1[4], b0[4], b1[4];
            *(float4*)a0 = *(const float4*)&As[buf][k][ty * 4];
            *(float4*)a1 = *(const float4*)&As[buf][k][64 + ty * 4];
            *(float4*)b0 = *(const float4*)&Bs[buf][k][tx * 4];
            *(float4*)b1 = *(const float4*)&Bs[buf][k][64 + tx * 4];
#pragma unroll
            for (int i = 0; i < 4; i++)
#pragma unroll
                for (int j = 0; j < 4; j++) {
                    acc[i][j]         += a0[i] * b0[j];
                    acc[i][j + 4]     += a0[i] * b1[j];
                    acc[i + 4][j]     += a1[i] * b0[j];
                    acc[i + 4][j + 4] += a1[i] * b1[j];
                }
        }
        buf ^= 1;
    }

    float bv0[4], bv1[4];
#pragma unroll
    for (int j = 0; j < 4; j++) {
        bv0[j] = bias ? bias[bn + tx * 4 + j]      : 0.f;
        bv1[j] = bias ? bias[bn + 64 + tx * 4 + j] : 0.f;
    }

#pragma unroll
    for (int i = 0; i < 8; i++) {
        int r = bm + ((i < 4) ? (ty * 4 + i) : (64 + ty * 4 + (i - 4)));
        float4 o0, o1;
        o0.x = acc[i][0] + bv0[0]; o0.y = acc[i][1] + bv0[1];
        o0.z = acc[i][2] + bv0[2]; o0.w = acc[i][3] + bv0[3];
        o1.x = acc[i][4] + bv1[0]; o1.y = acc[i][5] + bv1[1];
        o1.z = acc[i][6] + bv1[2]; o1.w = acc[i][7] + bv1[3];
        *(float4*)&C[(size_t)r * N + bn + tx * 4]      = o0;
        *(float4*)&C[(size_t)r * N + bn + 64 + tx * 4] = o1;
    }
}

// ---------------------------------------------------------------------------
// Sequential scan, 2-CTA cluster per batch row, mbarrier handshake.
// Rank r computes output columns [r*128, r*128+128).
// Thread i: cl = i&127 (local column), half = i>>7.
//   half 0 (warps 0-3): k over OWN column range  (local data, no wait)
//   half 1 (warps 4-7): k over PEER column range (waits on mbarrier)
// W_rec slice in registers (128 regs/thread). Spike halves exchanged via
// st.shared::cluster + remote mbarrier.arrive.release.cluster.
// ---------------------------------------------------------------------------
__global__ __launch_bounds__(256, 1) __cluster_dims__(2, 1, 1)
void scan_kernel(
    const float* __restrict__ W_rec, const float* __restrict__ spike0,
    const float* __restrict__ v0,    const float* __restrict__ xw,
    float* __restrict__ spikes, float* __restrict__ probs,
    float* __restrict__ vT, float* __restrict__ sT)
{
    __shared__ float sbuf[2][256];           // double-buffered spike vector
    __shared__ float part[128];              // peer-half partial sums
    __shared__ __align__(8) uint64_t mbar;   // arrival barrier (expect 128)

    const int i    = threadIdx.x;
    const int cl   = i & 127;
    const int half = i >> 7;
    const int row  = blockIdx.x >> 1;
    const int rank = blockIdx.x & 1;
    const int col  = rank * 128 + cl;        // global output column

    // k-range for this thread: half 0 -> own rank's cols, half 1 -> peer's
    const int kbase = (half == 0) ? rank * 128 : (rank ^ 1) * 128;

    // Register-resident W_rec slice: rows [kbase, kbase+128), column col
    float wreg[128];
#pragma unroll
    for (int j = 0; j < 128; j++)
        wreg[j] = W_rec[(size_t)(kbase + j) * 256 + col];

    // smem addresses (local + peer)
    uint32_t sbuf_u32, mbar_u32;
    {
        uint64_t tmp;
        asm("cvta.to.shared.u64 %0, %1;" : "=l"(tmp) : "l"((void*)&sbuf[0][0]));
        sbuf_u32 = (uint32_t)tmp;
        asm("cvta.to.shared.u64 %0, %1;" : "=l"(tmp) : "l"((void*)&mbar));
        mbar_u32 = (uint32_t)tmp;
    }
    const uint32_t peer = rank ^ 1;
    uint32_t r_sbuf, r_mbar;
    asm("mapa.shared::cluster.u32 %0, %1, %2;" : "=r"(r_sbuf) : "r"(sbuf_u32), "r"(peer));
    asm("mapa.shared::cluster.u32 %0, %1, %2;" : "=r"(r_mbar) : "r"(mbar_u32), "r"(peer));

    if (i == 0) {
        asm volatile("mbarrier.init.shared.b64 [%0], 128;" :: "r"(mbar_u32) : "memory");
    }

    // Init spike buffer (full vector) + spikes[0]
    sbuf[0][i] = spike0[row * 256 + i];
    spikes[(size_t)row * 256 + i] = spike0[row * 256 + i];

    float v = 0.f, prob = 0.f;
    if (half == 0) {
        v = v0[row * 256 + col];
        prob = spike0[row * 256 + col];
    }

    const float* xwp = xw + (size_t)row * 256 + col;   // half 0 only
    float xnext = (half == 0) ? __ldg(xwp) : 0.f;

    // One-time cluster sync: mbar init + sbuf[0] visible cluster-wide
    asm volatile("barrier.cluster.arrive.aligned;" ::: "memory");
    asm volatile("barrier.cluster.wait.aligned;"   ::: "memory");

    int cur = 0;
    unsigned ph = 0;   // mbarrier phase parity for half-1 waits

    for (int step = 0; step < T_STEPS; step++) {
        const float xval = xnext;
        if (half == 0 && step + 1 < T_STEPS)
            xnext = __ldg(xwp + (size_t)(step + 1) * (B_SZ * H_SZ));

        if (half == 1 && step > 0) {
            // Wait for peer's 128 spike pushes (acquire at cluster scope)
            uint32_t done;
            asm volatile(
                "{\n\t"
                ".reg .pred p;\n\t"
                "mbarrier.try_wait.parity.acquire.cluster.shared::cta.b64 p, [%1], %2;\n\t"
                "selp.b32 %0, 1, 0, p;\n\t"
                "}" : "=r"(done) : "r"(mbar_u32), "r"(ph) : "memory");
            if (!done) {
                asm volatile(
                    "{\n\t"
                    ".reg .pred P1;\n\t"
                    "W0_%=:\n\t"
                    "mbarrier.try_wait.parity.acquire.cluster.shared::cta.b64 P1, [%0], %1, 0x989680;\n\t"
                    "@P1 bra.uni W1_%=;\n\t"
                    "bra.uni W0_%=;\n\t"
                    "W1_%=:\n\t"
                    "}" :: "r"(mbar_u32), "r"(ph) : "memory");
            }
            ph ^= 1;
        }

        // Dot over this thread's k-range (W in regs, s is broadcast LDS)
        const float* s = &sbuf[cur][kbase];
        float acc = 0.f;
#pragma unroll
        for (int j = 0; j < 128; j += 4) {
            float4 sv = *(const float4*)(s + j);
            acc += sv.x * wreg[j + 0];
            acc += sv.y * wreg[j + 1];
            acc += sv.z * wreg[j + 2];
            acc += sv.w * wreg[j + 3];
        }

        if (half == 1) part[cl] = acc;
        __syncthreads();   // sync#1: part ready; all reads of sbuf[cur] done

        const int nxt = cur ^ 1;
        if (half == 0) {
            float tot = acc + part[cl];
            v = ALPHA * v + xval + tot;
            prob = 1.0f / (1.0f + __expf(-v));

            const size_t off = ((size_t)step * B_SZ + row) * 256 + col;
            probs[off] = prob;                        // probs[step]
            spikes[off + (size_t)B_SZ * 256] = prob;  // spikes[step+1]

            // local spike buffer
            sbuf[nxt][col] = prob;

            if (step + 1 < T_STEPS) {
                // push to peer + release-arrive on peer's mbarrier
                uint32_t raddr = r_sbuf + (uint32_t)((nxt * 256 + col) * 4);
                asm volatile("st.shared::cluster.f32 [%0], %1;"
                             :: "r"(raddr), "f"(prob) : "memory");
                asm volatile("mbarrier.arrive.release.cluster.shared::cluster.b64 _, [%0];"
                             :: "r"(r_mbar) : "memory");
            }
        }

        __syncthreads();   // sync#2: sbuf[nxt] local writes visible, part reusable
        cur = nxt;
    }

    if (half == 0) {
        vT[row * 256 + col] = v;
        sT[row * 256 + col] = prob;
    }

    // No CTA may exit while peer DSMEM ops could be in flight
    asm volatile("barrier.cluster.arrive.aligned;" ::: "memory");
    asm volatile("barrier.cluster.wait.aligned;"   ::: "memory");
}

// ---------------------------------------------------------------------------
// Launch: GEMM(xw) -> scan -> GEMM(preds). All stream-ordered, capture-safe.
// ---------------------------------------------------------------------------
extern "C" void kernel_launch(void* const* d_in, const int* in_sizes, int n_in,
                              void* d_out, int out_size)
{
    const float* inputs = (const float*)d_in[0];  // [512,64,256]
    const float* spike0 = (const float*)d_in[1];  // [64,256]
    const float* v0     = (const float*)d_in[2];  // [64,256]
    const float* W_in   = (const float*)d_in[3];  // [256,256]
    const float* W_rec  = (const float*)d_in[4];  // [256,256]
    const float* W_out  = (const float*)d_in[5];  // [256,256]
    const float* bvec   = (const float*)d_in[6];  // [256]

    float* out = (float*)d_out;
    float* spikes = out;
    float* preds  = out + (size_t)513 * B_SZ * H_SZ;
    float* probs  = preds + (size_t)T_STEPS * B_SZ * H_SZ;
    float* vT     = probs + (size_t)T_STEPS * B_SZ * H_SZ;
    float* sT     = vT + (size_t)B_SZ * H_SZ;

    float* xw = nullptr;
    cudaGetSymbolAddress((void**)&xw, g_xw);

    dim3 gemm_grid((T_STEPS * B_SZ) / 128, H_SZ / 128);  // (256, 2)

    // 1) xw = inputs @ W_in + b
    sgemm_k<<<gemm_grid, 256>>>(inputs, W_in, bvec, xw);

    // 2) sequential scan (128 CTAs = 64 clusters of 2)
    scan_kernel<<<2 * B_SZ, 256>>>(W_rec, spike0, v0, xw,
                                   spikes, probs, vT, sT);

    // 3) preds = spikes[1:] @ W_out
    sgemm_k<<<gemm_grid, 256>>>(spikes + (size_t)B_SZ * H_SZ, W_out, nullptr, preds);
}

// round 5
// speedup vs baseline: 1.4019x; 1.0714x over previous
#include <cuda_runtime.h>
#include <cuda_bf16.h>
#include <cstdint>
#include <math.h>

// Problem dims (fixed by the dataset)
#define T_STEPS 512
#define B_SZ    64
#define D_SZ    256
#define H_SZ    256
#define ALPHA   0.9f

// Scratch for the precomputed input GEMM: xw[t][b][h] = inputs[t,b,:]@W_in + b
__device__ float g_xw[(size_t)T_STEPS * B_SZ * H_SZ];

// ---- f32x2 helpers (sm_103a packed fp32 FMA) --------------------------------
__device__ __forceinline__ unsigned long long pk2(float lo, float hi) {
    unsigned long long r;
    asm("mov.b64 %0, {%1, %2};" : "=l"(r) : "f"(lo), "f"(hi));
    return r;
}
__device__ __forceinline__ unsigned long long dup2(float a) {
    unsigned long long r;
    asm("mov.b64 %0, {%1, %1};" : "=l"(r) : "f"(a));
    return r;
}
__device__ __forceinline__ void fma2(unsigned long long& acc,
                                     unsigned long long a, unsigned long long b) {
    asm("fma.rn.f32x2 %0, %1, %2, %0;" : "+l"(acc) : "l"(a), "l"(b));
}
__device__ __forceinline__ float2 unpk(unsigned long long v) {
    float lo, hi;
    asm("mov.b64 {%0, %1}, %2;" : "=f"(lo), "=f"(hi) : "l"(v));
    return make_float2(lo, hi);
}

// ---------------------------------------------------------------------------
// Tiled fp32 GEMM with FFMA2: C[M,256] = A[M,256] @ Bm[256,256] (+ bias).
// Tiles 128x128, BK=8, 256 threads, 8x8 per thread (as 8x4 f32x2 accs).
// ---------------------------------------------------------------------------
__global__ __launch_bounds__(256) void sgemm_k(
    const float* __restrict__ A, const float* __restrict__ Bm,
    const float* __restrict__ bias, float* __restrict__ C)
{
    const int K = 256, N = 256;
    __shared__ float As[2][8][128];
    __shared__ float Bs[2][8][128];

    const int tid = threadIdx.x;
    const int bm = blockIdx.x * 128;
    const int bn = blockIdx.y * 128;
    const int tx = tid & 15;
    const int ty = tid >> 4;

    const int a_m = tid >> 1;
    const int a_k = (tid & 1) * 4;
    const int b_k = tid >> 5;
    const int b_n = (tid & 31) * 4;

    const float* Ap = A + (size_t)(bm + a_m) * K + a_k;
    const float* Bp = Bm + (size_t)b_k * N + bn + b_n;

    float4 af = *(const float4*)Ap;
    float4 bf = *(const float4*)Bp;

    // acc2[i][0..1] -> cols tx*4 + {0,1},{2,3}; acc2[i][2..3] -> 64+tx*4 + ...
    unsigned long long acc2[8][4];
#pragma unroll
    for (int i = 0; i < 8; i++)
#pragma unroll
        for (int j = 0; j < 4; j++) acc2[i][j] = 0ull;

    int buf = 0;
    for (int kt = 0; kt < K; kt += 8) {
        As[buf][a_k + 0][a_m] = af.x;
        As[buf][a_k + 1][a_m] = af.y;
        As[buf][a_k + 2][a_m] = af.z;
        As[buf][a_k + 3][a_m] = af.w;
        *(float4*)&Bs[buf][b_k][b_n] = bf;
        __syncthreads();
        if (kt + 8 < K) {
            af = *(const float4*)(Ap + kt + 8);
            bf = *(const float4*)(Bp + (size_t)(kt + 8) * N);
        }
#pragma unroll
        for (int k = 0; k < 8; k++) {
            float4 a0 = *(const float4*)&As[buf][k][ty * 4];
            float4 a1 = *(const float4*)&As[buf][k][64 + ty * 4];
            ulonglong2 bx0 = *(const ulonglong2*)&Bs[buf][k][tx * 4];
            ulonglong2 bx1 = *(const ulonglong2*)&Bs[buf][k][64 + tx * 4];
            float av[8] = {a0.x, a0.y, a0.z, a0.w, a1.x, a1.y, a1.z, a1.w};
#pragma unroll
            for (int i = 0; i < 8; i++) {
                unsigned long long ad = dup2(av[i]);
                fma2(acc2[i][0], ad, bx0.x);
                fma2(acc2[i][1], ad, bx0.y);
                fma2(acc2[i][2], ad, bx1.x);
                fma2(acc2[i][3], ad, bx1.y);
            }
        }
        buf ^= 1;
    }

    float bv0[4], bv1[4];
#pragma unroll
    for (int j = 0; j < 4; j++) {
        bv0[j] = bias ? bias[bn + tx * 4 + j]      : 0.f;
        bv1[j] = bias ? bias[bn + 64 + tx * 4 + j] : 0.f;
    }

#pragma unroll
    for (int i = 0; i < 8; i++) {
        int r = bm + ((i < 4) ? (ty * 4 + i) : (64 + ty * 4 + (i - 4)));
        float2 p0 = unpk(acc2[i][0]), p1 = unpk(acc2[i][1]);
        float2 p2 = unpk(acc2[i][2]), p3 = unpk(acc2[i][3]);
        float4 o0, o1;
        o0.x = p0.x + bv0[0]; o0.y = p0.y + bv0[1];
        o0.z = p1.x + bv0[2]; o0.w = p1.y + bv0[3];
        o1.x = p2.x + bv1[0]; o1.y = p2.y + bv1[1];
        o1.z = p3.x + bv1[2]; o1.w = p3.y + bv1[3];
        *(float4*)&C[(size_t)r * N + bn + tx * 4]      = o0;
        *(float4*)&C[(size_t)r * N + bn + 64 + tx * 4] = o1;
    }
}

// ---------------------------------------------------------------------------
// Sequential scan, 2-CTA cluster per batch row, mbarrier handshake.
// Rank r computes output columns [r*128, r*128+128).
// Thread i: cl = i&127 (local column), half = i>>7.
//   half 0 (warps 0-3): k over OWN column range  (local data, no wait)
//   half 1 (warps 4-7): k over PEER column range (waits on mbarrier)
// W_rec slice packed in f32x2 registers; dot = 64 FFMA2 over 4 accumulators.
// ---------------------------------------------------------------------------
__global__ __launch_bounds__(256, 1) __cluster_dims__(2, 1, 1)
void scan_kernel(
    const float* __restrict__ W_rec, const float* __restrict__ spike0,
    const float* __restrict__ v0,    const float* __restrict__ xw,
    float* __restrict__ spikes, float* __restrict__ probs,
    float* __restrict__ vT, float* __restrict__ sT)
{
    __shared__ __align__(16) float sbuf[2][256];   // double-buffered spikes
    __shared__ float part[128];                    // peer-half partial sums
    __shared__ __align__(8) uint64_t mbar;         // arrival barrier (expect 128)

    const int i    = threadIdx.x;
    const int cl   = i & 127;
    const int half = i >> 7;
    const int row  = blockIdx.x >> 1;
    const int rank = blockIdx.x & 1;
    const int col  = rank * 128 + cl;

    const int kbase = (half == 0) ? rank * 128 : (rank ^ 1) * 128;

    // Packed W_rec slice: rows [kbase, kbase+128), column col -> 64 f32x2
    unsigned long long wpk[64];
#pragma unroll
    for (int j = 0; j < 64; j++)
        wpk[j] = pk2(W_rec[(size_t)(kbase + 2 * j) * 256 + col],
                     W_rec[(size_t)(kbase + 2 * j + 1) * 256 + col]);

    // smem addresses (local + peer)
    uint32_t sbuf_u32, mbar_u32;
    {
        uint64_t tmp;
        asm("cvta.to.shared.u64 %0, %1;" : "=l"(tmp) : "l"((void*)&sbuf[0][0]));
        sbuf_u32 = (uint32_t)tmp;
        asm("cvta.to.shared.u64 %0, %1;" : "=l"(tmp) : "l"((void*)&mbar));
        mbar_u32 = (uint32_t)tmp;
    }
    const uint32_t peer = rank ^ 1;
    uint32_t r_sbuf, r_mbar;
    asm("mapa.shared::cluster.u32 %0, %1, %2;" : "=r"(r_sbuf) : "r"(sbuf_u32), "r"(peer));
    asm("mapa.shared::cluster.u32 %0, %1, %2;" : "=r"(r_mbar) : "r"(mbar_u32), "r"(peer));

    if (i == 0) {
        asm volatile("mbarrier.init.shared.b64 [%0], 128;" :: "r"(mbar_u32) : "memory");
    }

    sbuf[0][i] = spike0[row * 256 + i];
    spikes[(size_t)row * 256 + i] = spike0[row * 256 + i];

    float v = 0.f, prob = 0.f;
    if (half == 0) {
        v = v0[row * 256 + col];
        prob = spike0[row * 256 + col];
    }

    const float* xwp = xw + (size_t)row * 256 + col;   // half 0 only
    float xnext = (half == 0) ? __ldg(xwp) : 0.f;

    // One-time cluster sync: mbar init + sbuf[0] visible cluster-wide
    asm volatile("barrier.cluster.arrive.aligned;" ::: "memory");
    asm volatile("barrier.cluster.wait.aligned;"   ::: "memory");

    int cur = 0;
    unsigned ph = 0;

    for (int step = 0; step < T_STEPS; step++) {
        const float xval = xnext;
        if (half == 0 && step + 1 < T_STEPS)
            xnext = __ldg(xwp + (size_t)(step + 1) * (B_SZ * H_SZ));

        if (half == 1 && step > 0) {
            uint32_t done;
            asm volatile(
                "{\n\t"
                ".reg .pred p;\n\t"
                "mbarrier.try_wait.parity.acquire.cluster.shared::cta.b64 p, [%1], %2;\n\t"
                "selp.b32 %0, 1, 0, p;\n\t"
                "}" : "=r"(done) : "r"(mbar_u32), "r"(ph) : "memory");
            if (!done) {
                asm volatile(
                    "{\n\t"
                    ".reg .pred P1;\n\t"
                    "W0_%=:\n\t"
                    "mbarrier.try_wait.parity.acquire.cluster.shared::cta.b64 P1, [%0], %1, 0x989680;\n\t"
                    "@P1 bra.uni W1_%=;\n\t"
                    "bra.uni W0_%=;\n\t"
                    "W1_%=:\n\t"
                    "}" :: "r"(mbar_u32), "r"(ph) : "memory");
            }
            ph ^= 1;
        }

        // Dot over this thread's 128-k range: 64 FFMA2, 4 f32x2 accumulators
        const ulonglong2* sp = (const ulonglong2*)&sbuf[cur][kbase];
        unsigned long long a4[4] = {0ull, 0ull, 0ull, 0ull};
#pragma unroll
        for (int j = 0; j < 32; j++) {
            ulonglong2 sv = sp[j];
            fma2(a4[(2 * j) & 3],     wpk[2 * j],     sv.x);
            fma2(a4[(2 * j + 1) & 3], wpk[2 * j + 1], sv.y);
        }
        float2 q0 = unpk(a4[0]), q1 = unpk(a4[1]), q2 = unpk(a4[2]), q3 = unpk(a4[3]);
        float acc = ((q0.x + q0.y) + (q1.x + q1.y)) + ((q2.x + q2.y) + (q3.x + q3.y));

        if (half == 1) part[cl] = acc;
        __syncthreads();   // sync#1: part ready; all reads of sbuf[cur] done

        const int nxt = cur ^ 1;
        if (half == 0) {
            float tot = acc + part[cl];
            v = ALPHA * v + xval + tot;
            prob = 1.0f / (1.0f + __expf(-v));

            const size_t off = ((size_t)step * B_SZ + row) * 256 + col;
            probs[off] = prob;                        // probs[step]
            spikes[off + (size_t)B_SZ * 256] = prob;  // spikes[step+1]

            sbuf[nxt][col] = prob;

            if (step + 1 < T_STEPS) {
                uint32_t raddr = r_sbuf + (uint32_t)((nxt * 256 + col) * 4);
                asm volatile("st.shared::cluster.f32 [%0], %1;"
                             :: "r"(raddr), "f"(prob) : "memory");
                asm volatile("mbarrier.arrive.release.cluster.shared::cluster.b64 _, [%0];"
                             :: "r"(r_mbar) : "memory");
            }
        }

        __syncthreads();   // sync#2: sbuf[nxt] local writes visible, part reusable
        cur = nxt;
    }

    if (half == 0) {
        vT[row * 256 + col] = v;
        sT[row * 256 + col] = prob;
    }

    asm volatile("barrier.cluster.arrive.aligned;" ::: "memory");
    asm volatile("barrier.cluster.wait.aligned;"   ::: "memory");
}

// ---------------------------------------------------------------------------
// Launch: GEMM(xw) -> scan -> GEMM(preds). All stream-ordered, capture-safe.
// ---------------------------------------------------------------------------
extern "C" void kernel_launch(void* const* d_in, const int* in_sizes, int n_in,
                              void* d_out, int out_size)
{
    const float* inputs = (const float*)d_in[0];  // [512,64,256]
    const float* spike0 = (const float*)d_in[1];  // [64,256]
    const float* v0     = (const float*)d_in[2];  // [64,256]
    const float* W_in   = (const float*)d_in[3];  // [256,256]
    const float* W_rec  = (const float*)d_in[4];  // [256,256]
    const float* W_out  = (const float*)d_in[5];  // [256,256]
    const float* bvec   = (const float*)d_in[6];  // [256]

    float* out = (float*)d_out;
    float* spikes = out;
    float* preds  = out + (size_t)513 * B_SZ * H_SZ;
    float* probs  = preds + (size_t)T_STEPS * B_SZ * H_SZ;
    float* vT     = probs + (size_t)T_STEPS * B_SZ * H_SZ;
    float* sT     = vT + (size_t)B_SZ * H_SZ;

    float* xw = nullptr;
    cudaGetSymbolAddress((void**)&xw, g_xw);

    dim3 gemm_grid((T_STEPS * B_SZ) / 128, H_SZ / 128);  // (256, 2)

    // 1) xw = inputs @ W_in + b
    sgemm_k<<<gemm_grid, 256>>>(inputs, W_in, bvec, xw);

    // 2) sequential scan (128 CTAs = 64 clusters of 2)
    scan_kernel<<<2 * B_SZ, 256>>>(W_rec, spike0, v0, xw,
                                   spikes, probs, vT, sT);

    // 3) preds = spikes[1:] @ W_out
    sgemm_k<<<gemm_grid, 256>>>(spikes + (size_t)B_SZ * H_SZ, W_out, nullptr, preds);
}

// round 6
// speedup vs baseline: 1.4483x; 1.0331x over previous
#include <cuda_runtime.h>
#include <cuda_bf16.h>
#include <cstdint>
#include <math.h>

// Problem dims (fixed by the dataset)
#define T_STEPS 512
#define B_SZ    64
#define D_SZ    256
#define H_SZ    256
#define ALPHA   0.9f

// Scratch for the precomputed input GEMM: xw[t][b][h] = inputs[t,b,:]@W_in + b
__device__ float g_xw[(size_t)T_STEPS * B_SZ * H_SZ];

// ---- f32x2 helpers (sm_103a packed fp32 FMA) --------------------------------
__device__ __forceinline__ unsigned long long pk2(float lo, float hi) {
    unsigned long long r;
    asm("mov.b64 %0, {%1, %2};" : "=l"(r) : "f"(lo), "f"(hi));
    return r;
}
__device__ __forceinline__ unsigned long long dup2(float a) {
    unsigned long long r;
    asm("mov.b64 %0, {%1, %1};" : "=l"(r) : "f"(a));
    return r;
}
__device__ __forceinline__ void fma2(unsigned long long& acc,
                                     unsigned long long a, unsigned long long b) {
    asm("fma.rn.f32x2 %0, %1, %2, %0;" : "+l"(acc) : "l"(a), "l"(b));
}
__device__ __forceinline__ float2 unpk(unsigned long long v) {
    float lo, hi;
    asm("mov.b64 {%0, %1}, %2;" : "=f"(lo), "=f"(hi) : "l"(v));
    return make_float2(lo, hi);
}

// ---------------------------------------------------------------------------
// Tiled fp32 GEMM with FFMA2: C[M,256] = A[M,256] @ Bm[256,256] (+ bias).
// Tiles 128x128, BK=8, 256 threads, 8x8 per thread (as 8x4 f32x2 accs).
// ---------------------------------------------------------------------------
__global__ __launch_bounds__(256) void sgemm_k(
    const float* __restrict__ A, const float* __restrict__ Bm,
    const float* __restrict__ bias, float* __restrict__ C)
{
    const int K = 256, N = 256;
    __shared__ float As[2][8][128];
    __shared__ float Bs[2][8][128];

    const int tid = threadIdx.x;
    const int bm = blockIdx.x * 128;
    const int bn = blockIdx.y * 128;
    const int tx = tid & 15;
    const int ty = tid >> 4;

    const int a_m = tid >> 1;
    const int a_k = (tid & 1) * 4;
    const int b_k = tid >> 5;
    const int b_n = (tid & 31) * 4;

    const float* Ap = A + (size_t)(bm + a_m) * K + a_k;
    const float* Bp = Bm + (size_t)b_k * N + bn + b_n;

    float4 af = *(const float4*)Ap;
    float4 bf = *(const float4*)Bp;

    unsigned long long acc2[8][4];
#pragma unroll
    for (int i = 0; i < 8; i++)
#pragma unroll
        for (int j = 0; j < 4; j++) acc2[i][j] = 0ull;

    int buf = 0;
    for (int kt = 0; kt < K; kt += 8) {
        As[buf][a_k + 0][a_m] = af.x;
        As[buf][a_k + 1][a_m] = af.y;
        As[buf][a_k + 2][a_m] = af.z;
        As[buf][a_k + 3][a_m] = af.w;
        *(float4*)&Bs[buf][b_k][b_n] = bf;
        __syncthreads();
        if (kt + 8 < K) {
            af = *(const float4*)(Ap + kt + 8);
            bf = *(const float4*)(Bp + (size_t)(kt + 8) * N);
        }
#pragma unroll
        for (int k = 0; k < 8; k++) {
            float4 a0 = *(const float4*)&As[buf][k][ty * 4];
            float4 a1 = *(const float4*)&As[buf][k][64 + ty * 4];
            ulonglong2 bx0 = *(const ulonglong2*)&Bs[buf][k][tx * 4];
            ulonglong2 bx1 = *(const ulonglong2*)&Bs[buf][k][64 + tx * 4];
            float av[8] = {a0.x, a0.y, a0.z, a0.w, a1.x, a1.y, a1.z, a1.w};
#pragma unroll
            for (int i = 0; i < 8; i++) {
                unsigned long long ad = dup2(av[i]);
                fma2(acc2[i][0], ad, bx0.x);
                fma2(acc2[i][1], ad, bx0.y);
                fma2(acc2[i][2], ad, bx1.x);
                fma2(acc2[i][3], ad, bx1.y);
            }
        }
        buf ^= 1;
    }

    float bv0[4], bv1[4];
#pragma unroll
    for (int j = 0; j < 4; j++) {
        bv0[j] = bias ? bias[bn + tx * 4 + j]      : 0.f;
        bv1[j] = bias ? bias[bn + 64 + tx * 4 + j] : 0.f;
    }

#pragma unroll
    for (int i = 0; i < 8; i++) {
        int r = bm + ((i < 4) ? (ty * 4 + i) : (64 + ty * 4 + (i - 4)));
        float2 p0 = unpk(acc2[i][0]), p1 = unpk(acc2[i][1]);
        float2 p2 = unpk(acc2[i][2]), p3 = unpk(acc2[i][3]);
        float4 o0, o1;
        o0.x = p0.x + bv0[0]; o0.y = p0.y + bv0[1];
        o0.z = p1.x + bv0[2]; o0.w = p1.y + bv0[3];
        o1.x = p2.x + bv1[0]; o1.y = p2.y + bv1[1];
        o1.z = p3.x + bv1[2]; o1.w = p3.y + bv1[3];
        *(float4*)&C[(size_t)r * N + bn + tx * 4]      = o0;
        *(float4*)&C[(size_t)r * N + bn + 64 + tx * 4] = o1;
    }
}

// ---------------------------------------------------------------------------
// Sequential scan: 64 CTAs (one per batch row), 256 threads (thread = column).
// W_rec rows [0,192) register-resident as 96 f32x2 per thread; rows [192,256)
// in smem PRE-PACKED as f32x2 pairs so the dot is pure FFMA2.
// Spike vector double-buffered in smem; ONE __syncthreads per step.
// ---------------------------------------------------------------------------
#define WREG_PAIRS 96    // 192 rows in registers
#define WSM_PAIRS  32    // 64 rows in smem (32 packed pairs)

__global__ __launch_bounds__(256, 1) void scan_kernel(
    const float* __restrict__ W_rec, const float* __restrict__ spike0,
    const float* __restrict__ v0,    const float* __restrict__ xw,
    float* __restrict__ spikes, float* __restrict__ probs,
    float* __restrict__ vT, float* __restrict__ sT)
{
    extern __shared__ __align__(16) unsigned char dynsm[];
    unsigned long long* w2 = (unsigned long long*)dynsm;              // [32*256] packed W pairs
    float* sbuf = (float*)(w2 + WSM_PAIRS * 256);                     // [2][256]

    const int t   = threadIdx.x;   // output column
    const int row = blockIdx.x;    // batch row

    // Stage smem W pairs: w2[j*256+t] = (W[192+2j][t], W[193+2j][t])
#pragma unroll
    for (int j = 0; j < WSM_PAIRS; j++)
        w2[j * 256 + t] = pk2(W_rec[(size_t)(2 * WREG_PAIRS + 2 * j) * 256 + t],
                              W_rec[(size_t)(2 * WREG_PAIRS + 2 * j + 1) * 256 + t]);

    // Register-resident W pairs: rows [0,192)
    unsigned long long wpk[WREG_PAIRS];
#pragma unroll
    for (int j = 0; j < WREG_PAIRS; j++)
        wpk[j] = pk2(W_rec[(size_t)(2 * j) * 256 + t],
                     W_rec[(size_t)(2 * j + 1) * 256 + t]);

    const float s0 = spike0[row * 256 + t];
    sbuf[t] = s0;
    spikes[(size_t)row * 256 + t] = s0;          // spikes[0] = spike0
    float v = v0[row * 256 + t];
    float prob = s0;

    const float* xwp = xw + (size_t)row * 256 + t;
    float xnext = __ldg(xwp);

    __syncthreads();

    int cur = 0;
    for (int step = 0; step < T_STEPS; step++) {
        const float xval = xnext;
        if (step + 1 < T_STEPS)
            xnext = __ldg(xwp + (size_t)(step + 1) * (B_SZ * H_SZ));

        unsigned long long a4[4] = {0ull, 0ull, 0ull, 0ull};

        // Register part: k in [0,192), 48 LDS.128 of s, 96 FFMA2
        const ulonglong2* sp = (const ulonglong2*)&sbuf[cur * 256];
#pragma unroll
        for (int q = 0; q < WREG_PAIRS / 2; q++) {
            ulonglong2 sv = sp[q];
            fma2(a4[(2 * q) & 3],     wpk[2 * q],     sv.x);
            fma2(a4[(2 * q + 1) & 3], wpk[2 * q + 1], sv.y);
        }
        // Smem part: k in [192,256), W pairs from smem (LDS.64), 32 FFMA2
        const ulonglong2* sp2 = (const ulonglong2*)&sbuf[cur * 256 + 2 * WREG_PAIRS];
#pragma unroll
        for (int q = 0; q < WSM_PAIRS / 2; q++) {
            ulonglong2 sv = sp2[q];
            fma2(a4[0], w2[(2 * q) * 256 + t],     sv.x);
            fma2(a4[1], w2[(2 * q + 1) * 256 + t], sv.y);
        }

        float2 q0 = unpk(a4[0]), q1 = unpk(a4[1]), q2 = unpk(a4[2]), q3 = unpk(a4[3]);
        float acc = ((q0.x + q0.y) + (q1.x + q1.y)) + ((q2.x + q2.y) + (q3.x + q3.y));

        v = ALPHA * v + xval + acc;
        prob = 1.0f / (1.0f + __expf(-v));

        const size_t off = ((size_t)step * B_SZ + row) * 256 + t;
        probs[off] = prob;                        // probs[step]
        spikes[off + (size_t)B_SZ * 256] = prob;  // spikes[step+1]

        const int nxt = cur ^ 1;
        sbuf[nxt * 256 + t] = prob;
        __syncthreads();   // writes to nxt visible; prior reads of cur done
        cur = nxt;
    }

    vT[row * 256 + t] = v;
    sT[row * 256 + t] = prob;
}

// ---------------------------------------------------------------------------
// Launch: GEMM(xw) -> scan -> GEMM(preds). All stream-ordered, capture-safe.
// ---------------------------------------------------------------------------
extern "C" void kernel_launch(void* const* d_in, const int* in_sizes, int n_in,
                              void* d_out, int out_size)
{
    const float* inputs = (const float*)d_in[0];  // [512,64,256]
    const float* spike0 = (const float*)d_in[1];  // [64,256]
    const float* v0     = (const float*)d_in[2];  // [64,256]
    const float* W_in   = (const float*)d_in[3];  // [256,256]
    const float* W_rec  = (const float*)d_in[4];  // [256,256]
    const float* W_out  = (const float*)d_in[5];  // [256,256]
    const float* bvec   = (const float*)d_in[6];  // [256]

    float* out = (float*)d_out;
    float* spikes = out;
    float* preds  = out + (size_t)513 * B_SZ * H_SZ;
    float* probs  = preds + (size_t)T_STEPS * B_SZ * H_SZ;
    float* vT     = probs + (size_t)T_STEPS * B_SZ * H_SZ;
    float* sT     = vT + (size_t)B_SZ * H_SZ;

    float* xw = nullptr;
    cudaGetSymbolAddress((void**)&xw, g_xw);

    const size_t scan_smem = (size_t)WSM_PAIRS * 256 * 8 + 2 * 256 * sizeof(float);
    cudaFuncSetAttribute(scan_kernel, cudaFuncAttributeMaxDynamicSharedMemorySize,
                         (int)scan_smem);

    dim3 gemm_grid((T_STEPS * B_SZ) / 128, H_SZ / 128);  // (256, 2)

    // 1) xw = inputs @ W_in + b
    sgemm_k<<<gemm_grid, 256>>>(inputs, W_in, bvec, xw);

    // 2) sequential scan (64 CTAs, one per batch row)
    scan_kernel<<<B_SZ, 256, scan_smem>>>(W_rec, spike0, v0, xw,
                                          spikes, probs, vT, sT);

    // 3) preds = spikes[1:] @ W_out
    sgemm_k<<<gemm_grid, 256>>>(spikes + (size_t)B_SZ * H_SZ, W_out, nullptr, preds);
}